// round 1
// baseline (speedup 1.0000x reference)
#include <cuda_runtime.h>
#include <math.h>

#define BB 64
#define LC 1024
#define LQ 128
#define DD 128
#define NEG (-1e9f)

// ---------------- device scratch (no allocations allowed) ----------------
__device__ float g_S[(size_t)BB * LC * LQ];      // raw S (unmasked), 32 MB
__device__ float g_cdot[BB * LC];
__device__ float g_qdot[BB * LQ];
__device__ float g_rmax[BB * LC];
__device__ float g_rinv[BB * LC];
__device__ float g_cpm[BB * 8 * LQ];             // partial col max
__device__ float g_cps[BB * 8 * LQ];             // partial col sum
__device__ float g_cmax[BB * LQ];
__device__ float g_cinv[BB * LQ];
__device__ float g_V2p[(size_t)8 * BB * LQ * DD]; // split-K partials (deterministic)
__device__ float g_V2[BB * LQ * DD];             // S2^T @ C

// ---------------- K0: row dots (C.w_c -> cdot, Q.w_q -> qdot) -------------
__global__ __launch_bounds__(256) void dots_kernel(
    const float* __restrict__ Cg, const float* __restrict__ Qg,
    const float* __restrict__ w_c, const float* __restrict__ w_q) {
    int warp = (blockIdx.x * blockDim.x + threadIdx.x) >> 5;
    int lane = threadIdx.x & 31;
    if (warp < BB * LC) {
        const float* row = Cg + (size_t)warp * DD;
        float4 v = ((const float4*)row)[lane];
        float4 w = ((const float4*)w_c)[lane];
        float s = v.x * w.x + v.y * w.y + v.z * w.z + v.w * w.w;
        #pragma unroll
        for (int o = 16; o; o >>= 1) s += __shfl_xor_sync(0xffffffffu, s, o);
        if (lane == 0) g_cdot[warp] = s;
    } else {
        int r = warp - BB * LC;
        if (r < BB * LQ) {
            const float* row = Qg + (size_t)r * DD;
            float4 v = ((const float4*)row)[lane];
            float4 w = ((const float4*)w_q)[lane];
            float s = v.x * w.x + v.y * w.y + v.z * w.z + v.w * w.w;
            #pragma unroll
            for (int o = 16; o; o >>= 1) s += __shfl_xor_sync(0xffffffffu, s, o);
            if (lane == 0) g_qdot[r] = s;
        }
    }
}

// ---------------- K1: S = (C*w_mul) @ Q^T + cdot + qdot + bias -----------
// block: 256 thr, computes 64(i) x 128(j) tile; grid = BB*16
__global__ __launch_bounds__(256) void s_kernel(
    const float* __restrict__ Cg, const float* __restrict__ Qg,
    const float* __restrict__ w_mul, const float* __restrict__ bias) {
    __shared__ float As[32][64];    // [k][i]
    __shared__ float Bs[32][128];   // [k][j]
    int bx = blockIdx.x;
    int b = bx >> 4;
    int i0 = (bx & 15) << 6;
    int t = threadIdx.x;
    int ty = t >> 4;   // 0..15 -> i = ty*4
    int tx = t & 15;   // 0..15 -> j = tx*8

    float acc[4][8];
    #pragma unroll
    for (int r = 0; r < 4; r++)
        #pragma unroll
        for (int c = 0; c < 8; c++) acc[r][c] = 0.f;

    const float* Cb = Cg + ((size_t)b * LC + i0) * DD;
    const float* Qb = Qg + (size_t)b * LQ * DD;

    for (int kk = 0; kk < DD; kk += 32) {
        {   // load As (transposed), fold in w_mul
            int i = t >> 2;
            int k0 = (t & 3) << 3;
            const float* src = Cb + (size_t)i * DD + kk + k0;
            float4 v0 = *(const float4*)src;
            float4 v1 = *(const float4*)(src + 4);
            const float* wm = w_mul + kk + k0;
            As[k0 + 0][i] = v0.x * wm[0];
            As[k0 + 1][i] = v0.y * wm[1];
            As[k0 + 2][i] = v0.z * wm[2];
            As[k0 + 3][i] = v0.w * wm[3];
            As[k0 + 4][i] = v1.x * wm[4];
            As[k0 + 5][i] = v1.y * wm[5];
            As[k0 + 6][i] = v1.z * wm[6];
            As[k0 + 7][i] = v1.w * wm[7];
        }
        {   // load Bs (transposed)
            int j = t >> 1;
            int k0 = (t & 1) << 4;
            const float* src = Qb + (size_t)j * DD + kk + k0;
            #pragma unroll
            for (int u = 0; u < 16; u += 4) {
                float4 v = *(const float4*)(src + u);
                Bs[k0 + u + 0][j] = v.x;
                Bs[k0 + u + 1][j] = v.y;
                Bs[k0 + u + 2][j] = v.z;
                Bs[k0 + u + 3][j] = v.w;
            }
        }
        __syncthreads();
        #pragma unroll
        for (int k = 0; k < 32; k++) {
            float4 a  = *(const float4*)&As[k][ty << 2];
            float4 b0 = *(const float4*)&Bs[k][tx << 3];
            float4 b1 = *(const float4*)&Bs[k][(tx << 3) + 4];
            float av[4] = {a.x, a.y, a.z, a.w};
            float bv[8] = {b0.x, b0.y, b0.z, b0.w, b1.x, b1.y, b1.z, b1.w};
            #pragma unroll
            for (int r = 0; r < 4; r++)
                #pragma unroll
                for (int c = 0; c < 8; c++)
                    acc[r][c] = fmaf(av[r], bv[c], acc[r][c]);
        }
        __syncthreads();
    }

    float bi = bias[0];
    float qd[8];
    #pragma unroll
    for (int c = 0; c < 8; c++) qd[c] = g_qdot[b * LQ + (tx << 3) + c];
    #pragma unroll
    for (int r = 0; r < 4; r++) {
        int i = i0 + (ty << 2) + r;
        float cd = g_cdot[b * LC + i] + bi;
        float* dst = g_S + ((size_t)(b * LC + i)) * LQ + (tx << 3);
        float4 o0 = make_float4(acc[r][0] + cd + qd[0], acc[r][1] + cd + qd[1],
                                acc[r][2] + cd + qd[2], acc[r][3] + cd + qd[3]);
        float4 o1 = make_float4(acc[r][4] + cd + qd[4], acc[r][5] + cd + qd[5],
                                acc[r][6] + cd + qd[6], acc[r][7] + cd + qd[7]);
        *(float4*)dst = o0;
        *(float4*)(dst + 4) = o1;
    }
}

// ---------------- K2a: row softmax stats (over j, qmask) ------------------
__global__ __launch_bounds__(256) void rowstats_kernel(const int* __restrict__ Qmask) {
    int wg = (blockIdx.x * blockDim.x + threadIdx.x) >> 5;
    int lane = threadIdx.x & 31;
    if (wg >= BB * LC) return;
    int b = wg / LC;
    const float* Srow = g_S + (size_t)wg * LQ;
    const int* qm = Qmask + b * LQ;
    float4 v = ((const float4*)Srow)[lane];
    int4 m = ((const int4*)qm)[lane];
    float x0 = m.x ? v.x : NEG;
    float x1 = m.y ? v.y : NEG;
    float x2 = m.z ? v.z : NEG;
    float x3 = m.w ? v.w : NEG;
    float mx = fmaxf(fmaxf(x0, x1), fmaxf(x2, x3));
    #pragma unroll
    for (int o = 16; o; o >>= 1) mx = fmaxf(mx, __shfl_xor_sync(0xffffffffu, mx, o));
    float s = expf(x0 - mx) + expf(x1 - mx) + expf(x2 - mx) + expf(x3 - mx);
    #pragma unroll
    for (int o = 16; o; o >>= 1) s += __shfl_xor_sync(0xffffffffu, s, o);
    if (lane == 0) { g_rmax[wg] = mx; g_rinv[wg] = 1.f / s; }
}

// ---------------- K2b: column softmax partials (over i, cmask) ------------
// grid = BB*8, block 128 (thread = j), each block owns 128 i's
__global__ __launch_bounds__(128) void colpart_kernel(const int* __restrict__ Cmask) {
    int b = blockIdx.x >> 3;
    int g = blockIdx.x & 7;
    int j = threadIdx.x;
    const float* Sb = g_S + ((size_t)b * LC + g * 128) * LQ + j;
    const int* cm = Cmask + b * LC + g * 128;
    float m = NEG, s = 0.f;
    #pragma unroll 4
    for (int i = 0; i < 128; i++) {
        float v = cm[i] ? Sb[(size_t)i * LQ] : NEG;
        float mn = fmaxf(m, v);
        s = s * expf(m - mn) + expf(v - mn);
        m = mn;
    }
    g_cpm[(b * 8 + g) * LQ + j] = m;
    g_cps[(b * 8 + g) * LQ + j] = s;
}

__global__ __launch_bounds__(256) void colmerge_kernel() {
    int idx = blockIdx.x * blockDim.x + threadIdx.x;
    if (idx >= BB * LQ) return;
    int b = idx / LQ, j = idx % LQ;
    float M = NEG;
    #pragma unroll
    for (int g = 0; g < 8; g++) M = fmaxf(M, g_cpm[(b * 8 + g) * LQ + j]);
    float S = 0.f;
    #pragma unroll
    for (int g = 0; g < 8; g++) S += g_cps[(b * 8 + g) * LQ + j] * expf(g_cpm[(b * 8 + g) * LQ + j] - M);
    g_cmax[idx] = M;
    g_cinv[idx] = 1.f / S;
}

// ---------------- K3: V2 partial = P2^T(chunk) @ C(chunk) ----------------
// grid = BB*8, block 256; output partial [128 j x 128 d] per chunk of 128 i's
__global__ __launch_bounds__(256) void v2_kernel(
    const float* __restrict__ Cg, const int* __restrict__ Cmask) {
    __shared__ float Ps[32][128];    // [i-k][j] (already exp'd/normalized)
    __shared__ float Cs[32][128];    // [i-k][d]
    __shared__ float s_cmax[128], s_cinv[128];
    int b = blockIdx.x >> 3;
    int g = blockIdx.x & 7;
    int t = threadIdx.x;
    int ty = t >> 4;   // j = ty*8
    int tx = t & 15;   // d = tx*8
    if (t < 128) { s_cmax[t] = g_cmax[b * LQ + t]; s_cinv[t] = g_cinv[b * LQ + t]; }
    __syncthreads();

    float acc[8][8];
    #pragma unroll
    for (int r = 0; r < 8; r++)
        #pragma unroll
        for (int c = 0; c < 8; c++) acc[r][c] = 0.f;

    const float* Sb = g_S + ((size_t)b * LC + g * 128) * LQ;
    const float* Cb = Cg + ((size_t)b * LC + g * 128) * DD;
    const int* cm = Cmask + b * LC + g * 128;

    for (int kk = 0; kk < 128; kk += 32) {
        {
            int i = t >> 3;          // 0..31
            int j0 = (t & 7) << 4;   // 0..112
            int msk = cm[kk + i];
            const float* src = Sb + (size_t)(kk + i) * LQ + j0;
            #pragma unroll
            for (int u = 0; u < 16; u += 4) {
                float4 v = *(const float4*)(src + u);
                float x0 = msk ? v.x : NEG;
                float x1 = msk ? v.y : NEG;
                float x2 = msk ? v.z : NEG;
                float x3 = msk ? v.w : NEG;
                Ps[i][j0 + u + 0] = expf(x0 - s_cmax[j0 + u + 0]) * s_cinv[j0 + u + 0];
                Ps[i][j0 + u + 1] = expf(x1 - s_cmax[j0 + u + 1]) * s_cinv[j0 + u + 1];
                Ps[i][j0 + u + 2] = expf(x2 - s_cmax[j0 + u + 2]) * s_cinv[j0 + u + 2];
                Ps[i][j0 + u + 3] = expf(x3 - s_cmax[j0 + u + 3]) * s_cinv[j0 + u + 3];
            }
            int d0 = (t & 7) << 4;
            const float* csrc = Cb + (size_t)(kk + i) * DD + d0;
            #pragma unroll
            for (int u = 0; u < 16; u += 4) {
                float4 v = *(const float4*)(csrc + u);
                Cs[i][d0 + u + 0] = v.x;
                Cs[i][d0 + u + 1] = v.y;
                Cs[i][d0 + u + 2] = v.z;
                Cs[i][d0 + u + 3] = v.w;
            }
        }
        __syncthreads();
        #pragma unroll
        for (int k = 0; k < 32; k++) {
            float4 a0 = *(const float4*)&Ps[k][ty << 3];
            float4 a1 = *(const float4*)&Ps[k][(ty << 3) + 4];
            float4 c0 = *(const float4*)&Cs[k][tx << 3];
            float4 c1 = *(const float4*)&Cs[k][(tx << 3) + 4];
            float av[8] = {a0.x, a0.y, a0.z, a0.w, a1.x, a1.y, a1.z, a1.w};
            float cv[8] = {c0.x, c0.y, c0.z, c0.w, c1.x, c1.y, c1.z, c1.w};
            #pragma unroll
            for (int r = 0; r < 8; r++)
                #pragma unroll
                for (int c = 0; c < 8; c++)
                    acc[r][c] = fmaf(av[r], cv[c], acc[r][c]);
        }
        __syncthreads();
    }

    float* Vp = g_V2p + (size_t)(b * 8 + g) * LQ * DD;
    #pragma unroll
    for (int r = 0; r < 8; r++) {
        float* dst = Vp + (size_t)((ty << 3) + r) * DD + (tx << 3);
        *(float4*)dst = make_float4(acc[r][0], acc[r][1], acc[r][2], acc[r][3]);
        *(float4*)(dst + 4) = make_float4(acc[r][4], acc[r][5], acc[r][6], acc[r][7]);
    }
}

__global__ __launch_bounds__(256) void v2reduce_kernel() {
    int vec = blockIdx.x * blockDim.x + threadIdx.x;  // float4 index
    const int per_b = LQ * DD / 4;                    // 4096
    if (vec >= BB * per_b) return;
    int b = vec / per_b;
    int off = vec % per_b;
    float4 s = make_float4(0.f, 0.f, 0.f, 0.f);
    #pragma unroll
    for (int g = 0; g < 8; g++) {
        float4 v = ((const float4*)(g_V2p + (size_t)(b * 8 + g) * LQ * DD))[off];
        s.x += v.x; s.y += v.y; s.z += v.z; s.w += v.w;
    }
    ((float4*)g_V2)[vec] = s;
}

// ---------------- K4: A = P1@Q, Bm = P1@V2, write [C, A, C*A, C*Bm] ------
// grid = BB*16, block 256, 64(i) x 128(d) output
__global__ __launch_bounds__(256) void final_kernel(
    const float* __restrict__ Cg, const float* __restrict__ Qg,
    const int* __restrict__ Qmask, float* __restrict__ out) {
    __shared__ float Ps[128][64];   // [j][i] 32KB
    __shared__ float Qs[8][128];    // 4KB
    __shared__ float Vs[8][128];    // 4KB
    int bx = blockIdx.x;
    int b = bx >> 4;
    int i0 = (bx & 15) << 6;
    int t = threadIdx.x;
    int ty = t >> 4;   // i = ty*4
    int tx = t & 15;   // d = tx*8

    {   // build normalized P1 tile (transposed)
        int i = t >> 2;          // 0..63
        int j0 = (t & 3) << 5;   // 0,32,64,96
        int gi = b * LC + i0 + i;
        float rm = g_rmax[gi], ri = g_rinv[gi];
        const float* Srow = g_S + (size_t)gi * LQ + j0;
        const int* qm = Qmask + b * LQ + j0;
        #pragma unroll
        for (int u = 0; u < 32; u += 4) {
            float4 v = *(const float4*)(Srow + u);
            int4 m = *(const int4*)(qm + u);
            Ps[j0 + u + 0][i] = expf((m.x ? v.x : NEG) - rm) * ri;
            Ps[j0 + u + 1][i] = expf((m.y ? v.y : NEG) - rm) * ri;
            Ps[j0 + u + 2][i] = expf((m.z ? v.z : NEG) - rm) * ri;
            Ps[j0 + u + 3][i] = expf((m.w ? v.w : NEG) - rm) * ri;
        }
    }
    __syncthreads();

    float accA[4][8], accB[4][8];
    #pragma unroll
    for (int r = 0; r < 4; r++)
        #pragma unroll
        for (int c = 0; c < 8; c++) { accA[r][c] = 0.f; accB[r][c] = 0.f; }

    const float* Qb = Qg + (size_t)b * LQ * DD;
    const float* Vb = g_V2 + (size_t)b * LQ * DD;

    for (int kk = 0; kk < LQ; kk += 8) {
        {
            int j = t >> 5;          // 0..7
            int d0 = (t & 31) << 2;  // 0..124
            float4 q = *(const float4*)(Qb + (size_t)(kk + j) * DD + d0);
            Qs[j][d0 + 0] = q.x; Qs[j][d0 + 1] = q.y; Qs[j][d0 + 2] = q.z; Qs[j][d0 + 3] = q.w;
            float4 v = *(const float4*)(Vb + (size_t)(kk + j) * DD + d0);
            Vs[j][d0 + 0] = v.x; Vs[j][d0 + 1] = v.y; Vs[j][d0 + 2] = v.z; Vs[j][d0 + 3] = v.w;
        }
        __syncthreads();
        #pragma unroll
        for (int k = 0; k < 8; k++) {
            float4 a = *(const float4*)&Ps[kk + k][ty << 2];
            float av[4] = {a.x, a.y, a.z, a.w};
            float4 q0 = *(const float4*)&Qs[k][tx << 3];
            float4 q1 = *(const float4*)&Qs[k][(tx << 3) + 4];
            float4 v0 = *(const float4*)&Vs[k][tx << 3];
            float4 v1 = *(const float4*)&Vs[k][(tx << 3) + 4];
            float qv[8] = {q0.x, q0.y, q0.z, q0.w, q1.x, q1.y, q1.z, q1.w};
            float vv[8] = {v0.x, v0.y, v0.z, v0.w, v1.x, v1.y, v1.z, v1.w};
            #pragma unroll
            for (int r = 0; r < 4; r++)
                #pragma unroll
                for (int c = 0; c < 8; c++) {
                    accA[r][c] = fmaf(av[r], qv[c], accA[r][c]);
                    accB[r][c] = fmaf(av[r], vv[c], accB[r][c]);
                }
        }
        __syncthreads();
    }

    float* ob = out + ((size_t)(b * LC + i0)) * (4 * DD);
    const float* Cb = Cg + ((size_t)(b * LC + i0)) * DD;
    int d = tx << 3;
    #pragma unroll
    for (int r = 0; r < 4; r++) {
        int i = (ty << 2) + r;
        const float* crow = Cb + (size_t)i * DD + d;
        float4 c0 = *(const float4*)crow;
        float4 c1 = *(const float4*)(crow + 4);
        float* orow = ob + (size_t)i * (4 * DD);
        // C
        *(float4*)(orow + d) = c0;
        *(float4*)(orow + d + 4) = c1;
        // A
        float4 a0 = make_float4(accA[r][0], accA[r][1], accA[r][2], accA[r][3]);
        float4 a1 = make_float4(accA[r][4], accA[r][5], accA[r][6], accA[r][7]);
        *(float4*)(orow + DD + d) = a0;
        *(float4*)(orow + DD + d + 4) = a1;
        // C*A
        *(float4*)(orow + 2 * DD + d) = make_float4(c0.x * a0.x, c0.y * a0.y, c0.z * a0.z, c0.w * a0.w);
        *(float4*)(orow + 2 * DD + d + 4) = make_float4(c1.x * a1.x, c1.y * a1.y, c1.z * a1.z, c1.w * a1.w);
        // C*Bm
        *(float4*)(orow + 3 * DD + d) = make_float4(c0.x * accB[r][0], c0.y * accB[r][1], c0.z * accB[r][2], c0.w * accB[r][3]);
        *(float4*)(orow + 3 * DD + d + 4) = make_float4(c1.x * accB[r][4], c1.y * accB[r][5], c1.z * accB[r][6], c1.w * accB[r][7]);
    }
}

// ---------------- launch ----------------
extern "C" void kernel_launch(void* const* d_in, const int* in_sizes, int n_in,
                              void* d_out, int out_size) {
    const float* C     = (const float*)d_in[0];
    const float* Q     = (const float*)d_in[1];
    const int*   Cmask = (const int*)d_in[2];
    const int*   Qmask = (const int*)d_in[3];
    const float* w_c   = (const float*)d_in[4];
    const float* w_q   = (const float*)d_in[5];
    const float* w_mul = (const float*)d_in[6];
    const float* bias  = (const float*)d_in[7];
    float* out = (float*)d_out;

    dots_kernel<<<(BB * LC + BB * LQ) / 8, 256>>>(C, Q, w_c, w_q);
    s_kernel<<<BB * 16, 256>>>(C, Q, w_mul, bias);
    rowstats_kernel<<<BB * LC / 8, 256>>>(Qmask);
    colpart_kernel<<<BB * 8, 128>>>(Cmask);
    colmerge_kernel<<<(BB * LQ + 255) / 256, 256>>>();
    v2_kernel<<<BB * 8, 256>>>(C, Cmask);
    v2reduce_kernel<<<(BB * LQ * DD / 4 + 255) / 256, 256>>>();
    final_kernel<<<BB * 16, 256>>>(C, Q, Qmask, out);
}

// round 2
// speedup vs baseline: 1.0492x; 1.0492x over previous
#include <cuda_runtime.h>
#include <math.h>

#define BB 64
#define LC 1024
#define LQ 128
#define DD 128
#define NEG (-1e9f)

typedef unsigned long long u64;

// ---------------- device scratch (no allocations allowed) ----------------
__device__ float g_S[(size_t)BB * LC * LQ];      // raw S (unmasked), 32 MB
__device__ float g_cdot[BB * LC];
__device__ float g_qdot[BB * LQ];
__device__ float g_rmax[BB * LC];
__device__ float g_rinv[BB * LC];
__device__ float g_cpm[BB * 16 * LQ];            // partial col max (16 chunks of 64 rows)
__device__ float g_cps[BB * 16 * LQ];            // partial col sum
__device__ float g_cmax[BB * LQ];
__device__ float g_cinv[BB * LQ];
__device__ float g_V2p[(size_t)8 * BB * LQ * DD]; // split-K partials (deterministic)
__device__ float g_V2[BB * LQ * DD];             // S2^T @ C

// ---------------- f32x2 helpers ----------------
__device__ __forceinline__ u64 pk2(float lo, float hi) {
    u64 r;
    asm("mov.b64 %0, {%1, %2};" : "=l"(r) : "f"(lo), "f"(hi));
    return r;
}
__device__ __forceinline__ void upk2(u64 p, float& lo, float& hi) {
    asm("mov.b64 {%0, %1}, %2;" : "=f"(lo), "=f"(hi) : "l"(p));
}
__device__ __forceinline__ void ffma2(u64& d, u64 a, u64 b) {
    asm("fma.rn.f32x2 %0, %1, %2, %3;" : "=l"(d) : "l"(a), "l"(b), "l"(d));
}

// ---------------- K0: row dots (C.w_c -> cdot, Q.w_q -> qdot) -------------
__global__ __launch_bounds__(256) void dots_kernel(
    const float* __restrict__ Cg, const float* __restrict__ Qg,
    const float* __restrict__ w_c, const float* __restrict__ w_q) {
    int warp = (blockIdx.x * blockDim.x + threadIdx.x) >> 5;
    int lane = threadIdx.x & 31;
    if (warp < BB * LC) {
        const float* row = Cg + (size_t)warp * DD;
        float4 v = ((const float4*)row)[lane];
        float4 w = ((const float4*)w_c)[lane];
        float s = v.x * w.x + v.y * w.y + v.z * w.z + v.w * w.w;
        #pragma unroll
        for (int o = 16; o; o >>= 1) s += __shfl_xor_sync(0xffffffffu, s, o);
        if (lane == 0) g_cdot[warp] = s;
    } else {
        int r = warp - BB * LC;
        if (r < BB * LQ) {
            const float* row = Qg + (size_t)r * DD;
            float4 v = ((const float4*)row)[lane];
            float4 w = ((const float4*)w_q)[lane];
            float s = v.x * w.x + v.y * w.y + v.z * w.z + v.w * w.w;
            #pragma unroll
            for (int o = 16; o; o >>= 1) s += __shfl_xor_sync(0xffffffffu, s, o);
            if (lane == 0) g_qdot[r] = s;
        }
    }
}

// ---------------- K1: S + fused row stats + fused col partials ------------
// block: 256 thr, 64(i) x 128(j) tile; grid = BB*16
__global__ __launch_bounds__(256) void s_kernel(
    const float* __restrict__ Cg, const float* __restrict__ Qg,
    const float* __restrict__ w_mul, const float* __restrict__ bias,
    const int* __restrict__ Qmask, const int* __restrict__ Cmask) {
    __shared__ float As[32][64];    // [k][i]
    __shared__ float Bs[32][128];   // [k][j]
    __shared__ float red[16][129];
    __shared__ float bcast[128];
    int bx = blockIdx.x;
    int b = bx >> 4;
    int tile = bx & 15;
    int i0 = tile << 6;
    int t = threadIdx.x;
    int ty = t >> 4;   // i = ty*4 + r
    int tx = t & 15;   // j = tx*8 + c

    u64 acc2[4][4];
    #pragma unroll
    for (int r = 0; r < 4; r++)
        #pragma unroll
        for (int p = 0; p < 4; p++) acc2[r][p] = 0ull;

    const float* Cb = Cg + ((size_t)b * LC + i0) * DD;
    const float* Qb = Qg + (size_t)b * LQ * DD;

    for (int kk = 0; kk < DD; kk += 32) {
        {   // load As (transposed), fold in w_mul
            int i = t >> 2;
            int k0 = (t & 3) << 3;
            const float* src = Cb + (size_t)i * DD + kk + k0;
            float4 v0 = *(const float4*)src;
            float4 v1 = *(const float4*)(src + 4);
            const float* wm = w_mul + kk + k0;
            As[k0 + 0][i] = v0.x * wm[0];
            As[k0 + 1][i] = v0.y * wm[1];
            As[k0 + 2][i] = v0.z * wm[2];
            As[k0 + 3][i] = v0.w * wm[3];
            As[k0 + 4][i] = v1.x * wm[4];
            As[k0 + 5][i] = v1.y * wm[5];
            As[k0 + 6][i] = v1.z * wm[6];
            As[k0 + 7][i] = v1.w * wm[7];
        }
        {   // load Bs (transposed)
            int j = t >> 1;
            int k0 = (t & 1) << 4;
            const float* src = Qb + (size_t)j * DD + kk + k0;
            #pragma unroll
            for (int u = 0; u < 16; u += 4) {
                float4 v = *(const float4*)(src + u);
                Bs[k0 + u + 0][j] = v.x;
                Bs[k0 + u + 1][j] = v.y;
                Bs[k0 + u + 2][j] = v.z;
                Bs[k0 + u + 3][j] = v.w;
            }
        }
        __syncthreads();
        #pragma unroll
        for (int k = 0; k < 32; k++) {
            float4 a = *(const float4*)&As[k][ty << 2];
            ulonglong2 b0 = *(const ulonglong2*)&Bs[k][tx << 3];
            ulonglong2 b1 = *(const ulonglong2*)&Bs[k][(tx << 3) + 4];
            u64 bp[4] = {b0.x, b0.y, b1.x, b1.y};
            u64 ap[4] = {pk2(a.x, a.x), pk2(a.y, a.y), pk2(a.z, a.z), pk2(a.w, a.w)};
            #pragma unroll
            for (int r = 0; r < 4; r++)
                #pragma unroll
                for (int p = 0; p < 4; p++)
                    ffma2(acc2[r][p], ap[r], bp[p]);
        }
        __syncthreads();
    }

    // ---- epilogue: finalize S values ----
    float sv[4][8];
    float bi = bias[0];
    float qd[8];
    #pragma unroll
    for (int c = 0; c < 8; c++) qd[c] = g_qdot[b * LQ + (tx << 3) + c];
    #pragma unroll
    for (int r = 0; r < 4; r++) {
        float cd = g_cdot[b * LC + i0 + (ty << 2) + r] + bi;
        #pragma unroll
        for (int p = 0; p < 4; p++) {
            float lo, hi;
            upk2(acc2[r][p], lo, hi);
            sv[r][2 * p]     = lo + cd + qd[2 * p];
            sv[r][2 * p + 1] = hi + cd + qd[2 * p + 1];
        }
        float* dst = g_S + ((size_t)(b * LC + i0 + (ty << 2) + r)) * LQ + (tx << 3);
        *(float4*)dst       = make_float4(sv[r][0], sv[r][1], sv[r][2], sv[r][3]);
        *(float4*)(dst + 4) = make_float4(sv[r][4], sv[r][5], sv[r][6], sv[r][7]);
    }

    // masks
    const int4* qmp = (const int4*)(Qmask + b * LQ + (tx << 3));
    int4 qa = qmp[0], qb2 = qmp[1];
    int qm[8] = {qa.x, qa.y, qa.z, qa.w, qb2.x, qb2.y, qb2.z, qb2.w};
    int cm[4];
    #pragma unroll
    for (int r = 0; r < 4; r++) cm[r] = Cmask[b * LC + i0 + (ty << 2) + r];

    // ---- row softmax stats (over j, qmask): reduce across tx (16-lane group)
    #pragma unroll
    for (int r = 0; r < 4; r++) {
        float m = NEG;
        #pragma unroll
        for (int c = 0; c < 8; c++) m = fmaxf(m, qm[c] ? sv[r][c] : NEG);
        #pragma unroll
        for (int o = 1; o < 16; o <<= 1) m = fmaxf(m, __shfl_xor_sync(0xffffffffu, m, o));
        float s = 0.f;
        #pragma unroll
        for (int c = 0; c < 8; c++) s += __expf((qm[c] ? sv[r][c] : NEG) - m);
        #pragma unroll
        for (int o = 1; o < 16; o <<= 1) s += __shfl_xor_sync(0xffffffffu, s, o);
        if (tx == 0) {
            int gi = b * LC + i0 + (ty << 2) + r;
            g_rmax[gi] = m;
            g_rinv[gi] = 1.f / s;
        }
    }

    // ---- col softmax partials (over 64 i's of this tile, cmask)
    #pragma unroll
    for (int c = 0; c < 8; c++) {
        float m = NEG;
        #pragma unroll
        for (int r = 0; r < 4; r++) m = fmaxf(m, cm[r] ? sv[r][c] : NEG);
        red[ty][(tx << 3) + c] = m;
    }
    __syncthreads();
    if (t < 128) {
        float m = NEG;
        #pragma unroll
        for (int g = 0; g < 16; g++) m = fmaxf(m, red[g][t]);
        bcast[t] = m;
    }
    __syncthreads();
    #pragma unroll
    for (int c = 0; c < 8; c++) {
        float mm = bcast[(tx << 3) + c];
        float s = 0.f;
        #pragma unroll
        for (int r = 0; r < 4; r++) s += cm[r] ? __expf(sv[r][c] - mm) : 0.f;
        red[ty][(tx << 3) + c] = s;
    }
    __syncthreads();
    if (t < 128) {
        float s = 0.f;
        #pragma unroll
        for (int g = 0; g < 16; g++) s += red[g][t];
        g_cpm[(b * 16 + tile) * LQ + t] = bcast[t];
        g_cps[(b * 16 + tile) * LQ + t] = s;
    }
}

// ---------------- K2: merge col partials ----------------
__global__ __launch_bounds__(256) void colmerge_kernel() {
    int idx = blockIdx.x * blockDim.x + threadIdx.x;
    if (idx >= BB * LQ) return;
    int b = idx >> 7, j = idx & 127;
    float M = NEG;
    #pragma unroll
    for (int g = 0; g < 16; g++) M = fmaxf(M, g_cpm[(b * 16 + g) * LQ + j]);
    float S = 0.f;
    #pragma unroll
    for (int g = 0; g < 16; g++) S += g_cps[(b * 16 + g) * LQ + j] * __expf(g_cpm[(b * 16 + g) * LQ + j] - M);
    g_cmax[idx] = M;
    g_cinv[idx] = 1.f / S;
}

// ---------------- K3: V2 partial = P2^T(chunk) @ C(chunk) ----------------
// grid = BB*8, block 256; output partial [128 j x 128 d] per chunk of 128 i's
__global__ __launch_bounds__(256) void v2_kernel(
    const float* __restrict__ Cg, const int* __restrict__ Cmask) {
    __shared__ float Ps[32][128];    // [i-k][j] (exp'd/normalized)
    __shared__ float Cs[32][128];    // [i-k][d]
    __shared__ float s_cmax[128], s_cinv[128];
    int b = blockIdx.x >> 3;
    int g = blockIdx.x & 7;
    int t = threadIdx.x;
    int ty = t >> 4;   // j = ty*8
    int tx = t & 15;   // d = tx*8
    if (t < 128) { s_cmax[t] = g_cmax[b * LQ + t]; s_cinv[t] = g_cinv[b * LQ + t]; }
    __syncthreads();

    u64 acc2[8][4];
    #pragma unroll
    for (int r = 0; r < 8; r++)
        #pragma unroll
        for (int p = 0; p < 4; p++) acc2[r][p] = 0ull;

    const float* Sb = g_S + ((size_t)b * LC + g * 128) * LQ;
    const float* Cb = Cg + ((size_t)b * LC + g * 128) * DD;
    const int* cm = Cmask + b * LC + g * 128;

    for (int kk = 0; kk < 128; kk += 32) {
        {
            int i = t >> 3;          // 0..31
            int j0 = (t & 7) << 4;   // 0..112
            int msk = cm[kk + i];
            const float* src = Sb + (size_t)(kk + i) * LQ + j0;
            #pragma unroll
            for (int u = 0; u < 16; u += 4) {
                float4 v = *(const float4*)(src + u);
                float x0 = msk ? v.x : NEG;
                float x1 = msk ? v.y : NEG;
                float x2 = msk ? v.z : NEG;
                float x3 = msk ? v.w : NEG;
                Ps[i][j0 + u + 0] = __expf(x0 - s_cmax[j0 + u + 0]) * s_cinv[j0 + u + 0];
                Ps[i][j0 + u + 1] = __expf(x1 - s_cmax[j0 + u + 1]) * s_cinv[j0 + u + 1];
                Ps[i][j0 + u + 2] = __expf(x2 - s_cmax[j0 + u + 2]) * s_cinv[j0 + u + 2];
                Ps[i][j0 + u + 3] = __expf(x3 - s_cmax[j0 + u + 3]) * s_cinv[j0 + u + 3];
            }
            int d0 = (t & 7) << 4;
            const float* csrc = Cb + (size_t)(kk + i) * DD + d0;
            #pragma unroll
            for (int u = 0; u < 16; u += 4) {
                float4 v = *(const float4*)(csrc + u);
                Cs[i][d0 + u + 0] = v.x;
                Cs[i][d0 + u + 1] = v.y;
                Cs[i][d0 + u + 2] = v.z;
                Cs[i][d0 + u + 3] = v.w;
            }
        }
        __syncthreads();
        #pragma unroll
        for (int k = 0; k < 32; k++) {
            float4 a0 = *(const float4*)&Ps[k][ty << 3];
            float4 a1 = *(const float4*)&Ps[k][(ty << 3) + 4];
            ulonglong2 c0 = *(const ulonglong2*)&Cs[k][tx << 3];
            ulonglong2 c1 = *(const ulonglong2*)&Cs[k][(tx << 3) + 4];
            u64 cp[4] = {c0.x, c0.y, c1.x, c1.y};
            u64 ap[8] = {pk2(a0.x, a0.x), pk2(a0.y, a0.y), pk2(a0.z, a0.z), pk2(a0.w, a0.w),
                         pk2(a1.x, a1.x), pk2(a1.y, a1.y), pk2(a1.z, a1.z), pk2(a1.w, a1.w)};
            #pragma unroll
            for (int r = 0; r < 8; r++)
                #pragma unroll
                for (int p = 0; p < 4; p++)
                    ffma2(acc2[r][p], ap[r], cp[p]);
        }
        __syncthreads();
    }

    float* Vp = g_V2p + (size_t)(b * 8 + g) * LQ * DD;
    #pragma unroll
    for (int r = 0; r < 8; r++) {
        float o[8];
        #pragma unroll
        for (int p = 0; p < 4; p++) upk2(acc2[r][p], o[2 * p], o[2 * p + 1]);
        float* dst = Vp + (size_t)((ty << 3) + r) * DD + (tx << 3);
        *(float4*)dst       = make_float4(o[0], o[1], o[2], o[3]);
        *(float4*)(dst + 4) = make_float4(o[4], o[5], o[6], o[7]);
    }
}

__global__ __launch_bounds__(256) void v2reduce_kernel() {
    int vec = blockIdx.x * blockDim.x + threadIdx.x;  // float4 index
    const int per_b = LQ * DD / 4;                    // 4096
    if (vec >= BB * per_b) return;
    int b = vec / per_b;
    int off = vec % per_b;
    float4 s = make_float4(0.f, 0.f, 0.f, 0.f);
    #pragma unroll
    for (int g = 0; g < 8; g++) {
        float4 v = ((const float4*)(g_V2p + (size_t)(b * 8 + g) * LQ * DD))[off];
        s.x += v.x; s.y += v.y; s.z += v.z; s.w += v.w;
    }
    ((float4*)g_V2)[vec] = s;
}

// ---------------- K4: A = P1@Q, Bm = P1@V2, write [C, A, C*A, C*Bm] ------
// grid = BB*16, block 256, 64(i) x 128(d) output
__global__ __launch_bounds__(256) void final_kernel(
    const float* __restrict__ Cg, const float* __restrict__ Qg,
    const int* __restrict__ Qmask, float* __restrict__ out) {
    __shared__ float Ps[128][64];   // [j][i] 32KB
    __shared__ float Qs[8][128];    // 4KB
    __shared__ float Vs[8][128];    // 4KB
    int bx = blockIdx.x;
    int b = bx >> 4;
    int i0 = (bx & 15) << 6;
    int t = threadIdx.x;
    int ty = t >> 4;   // i = ty*4
    int tx = t & 15;   // d = tx*8

    {   // build normalized P1 tile (transposed)
        int i = t >> 2;          // 0..63
        int j0 = (t & 3) << 5;   // 0,32,64,96
        int gi = b * LC + i0 + i;
        float rm = g_rmax[gi], ri = g_rinv[gi];
        const float* Srow = g_S + (size_t)gi * LQ + j0;
        const int* qm = Qmask + b * LQ + j0;
        #pragma unroll
        for (int u = 0; u < 32; u += 4) {
            float4 v = *(const float4*)(Srow + u);
            int4 m = *(const int4*)(qm + u);
            Ps[j0 + u + 0][i] = __expf((m.x ? v.x : NEG) - rm) * ri;
            Ps[j0 + u + 1][i] = __expf((m.y ? v.y : NEG) - rm) * ri;
            Ps[j0 + u + 2][i] = __expf((m.z ? v.z : NEG) - rm) * ri;
            Ps[j0 + u + 3][i] = __expf((m.w ? v.w : NEG) - rm) * ri;
        }
    }
    __syncthreads();

    u64 accA2[4][4], accB2[4][4];
    #pragma unroll
    for (int r = 0; r < 4; r++)
        #pragma unroll
        for (int p = 0; p < 4; p++) { accA2[r][p] = 0ull; accB2[r][p] = 0ull; }

    const float* Qb = Qg + (size_t)b * LQ * DD;
    const float* Vb = g_V2 + (size_t)b * LQ * DD;

    for (int kk = 0; kk < LQ; kk += 8) {
        {
            int j = t >> 5;          // 0..7
            int d0 = (t & 31) << 2;  // 0..124
            float4 q = *(const float4*)(Qb + (size_t)(kk + j) * DD + d0);
            Qs[j][d0 + 0] = q.x; Qs[j][d0 + 1] = q.y; Qs[j][d0 + 2] = q.z; Qs[j][d0 + 3] = q.w;
            float4 v = *(const float4*)(Vb + (size_t)(kk + j) * DD + d0);
            Vs[j][d0 + 0] = v.x; Vs[j][d0 + 1] = v.y; Vs[j][d0 + 2] = v.z; Vs[j][d0 + 3] = v.w;
        }
        __syncthreads();
        #pragma unroll
        for (int k = 0; k < 8; k++) {
            float4 a = *(const float4*)&Ps[kk + k][ty << 2];
            u64 ap[4] = {pk2(a.x, a.x), pk2(a.y, a.y), pk2(a.z, a.z), pk2(a.w, a.w)};
            ulonglong2 q0 = *(const ulonglong2*)&Qs[k][tx << 3];
            ulonglong2 q1 = *(const ulonglong2*)&Qs[k][(tx << 3) + 4];
            ulonglong2 v0 = *(const ulonglong2*)&Vs[k][tx << 3];
            ulonglong2 v1 = *(const ulonglong2*)&Vs[k][(tx << 3) + 4];
            u64 qp[4] = {q0.x, q0.y, q1.x, q1.y};
            u64 vp[4] = {v0.x, v0.y, v1.x, v1.y};
            #pragma unroll
            for (int r = 0; r < 4; r++)
                #pragma unroll
                for (int p = 0; p < 4; p++) {
                    ffma2(accA2[r][p], ap[r], qp[p]);
                    ffma2(accB2[r][p], ap[r], vp[p]);
                }
        }
        __syncthreads();
    }

    float* ob = out + ((size_t)(b * LC + i0)) * (4 * DD);
    const float* Cb = Cg + ((size_t)(b * LC + i0)) * DD;
    int d = tx << 3;
    #pragma unroll
    for (int r = 0; r < 4; r++) {
        int i = (ty << 2) + r;
        float aA[8], aB[8];
        #pragma unroll
        for (int p = 0; p < 4; p++) {
            upk2(accA2[r][p], aA[2 * p], aA[2 * p + 1]);
            upk2(accB2[r][p], aB[2 * p], aB[2 * p + 1]);
        }
        const float* crow = Cb + (size_t)i * DD + d;
        float4 c0 = *(const float4*)crow;
        float4 c1 = *(const float4*)(crow + 4);
        float* orow = ob + (size_t)i * (4 * DD);
        // C
        *(float4*)(orow + d) = c0;
        *(float4*)(orow + d + 4) = c1;
        // A
        *(float4*)(orow + DD + d)     = make_float4(aA[0], aA[1], aA[2], aA[3]);
        *(float4*)(orow + DD + d + 4) = make_float4(aA[4], aA[5], aA[6], aA[7]);
        // C*A
        *(float4*)(orow + 2 * DD + d)     = make_float4(c0.x * aA[0], c0.y * aA[1], c0.z * aA[2], c0.w * aA[3]);
        *(float4*)(orow + 2 * DD + d + 4) = make_float4(c1.x * aA[4], c1.y * aA[5], c1.z * aA[6], c1.w * aA[7]);
        // C*Bm
        *(float4*)(orow + 3 * DD + d)     = make_float4(c0.x * aB[0], c0.y * aB[1], c0.z * aB[2], c0.w * aB[3]);
        *(float4*)(orow + 3 * DD + d + 4) = make_float4(c1.x * aB[4], c1.y * aB[5], c1.z * aB[6], c1.w * aB[7]);
    }
}

// ---------------- launch ----------------
extern "C" void kernel_launch(void* const* d_in, const int* in_sizes, int n_in,
                              void* d_out, int out_size) {
    const float* C     = (const float*)d_in[0];
    const float* Q     = (const float*)d_in[1];
    const int*   Cmask = (const int*)d_in[2];
    const int*   Qmask = (const int*)d_in[3];
    const float* w_c   = (const float*)d_in[4];
    const float* w_q   = (const float*)d_in[5];
    const float* w_mul = (const float*)d_in[6];
    const float* bias  = (const float*)d_in[7];
    float* out = (float*)d_out;

    dots_kernel<<<(BB * LC + BB * LQ) / 8, 256>>>(C, Q, w_c, w_q);
    s_kernel<<<BB * 16, 256>>>(C, Q, w_mul, bias, Qmask, Cmask);
    colmerge_kernel<<<(BB * LQ + 255) / 256, 256>>>();
    v2_kernel<<<BB * 8, 256>>>(C, Cmask);
    v2reduce_kernel<<<(BB * LQ * DD / 4 + 255) / 256, 256>>>();
    final_kernel<<<BB * 16, 256>>>(C, Q, Qmask, out);
}

// round 3
// speedup vs baseline: 1.4672x; 1.3984x over previous
#include <cuda_runtime.h>
#include <math.h>
#include <stdint.h>

#define BB 64
#define LC 1024
#define LQ 128
#define DD 128
#define NEG (-1e9f)

// ---------------- device scratch ----------------
__device__ float g_S[(size_t)BB * LC * LQ];      // finalized S, 32 MB
__device__ float g_rmax[BB * LC];
__device__ float g_rinv[BB * LC];
__device__ float g_cpm[BB * 16 * LQ];
__device__ float g_cps[BB * 16 * LQ];
__device__ float g_cmax[BB * LQ];
__device__ float g_cinv[BB * LQ];
__device__ float g_V2p[(size_t)8 * BB * LQ * DD];
__device__ float g_V2[BB * LQ * DD];

// ---------------- tf32 mma helpers ----------------
__device__ __forceinline__ void split_tf32(float x, uint32_t& hi, uint32_t& lo) {
    asm("cvt.rna.tf32.f32 %0, %1;" : "=r"(hi) : "f"(x));
    float r = x - __uint_as_float(hi);
    asm("cvt.rna.tf32.f32 %0, %1;" : "=r"(lo) : "f"(r));
}
__device__ __forceinline__ void mma8(float* d, const uint32_t* a, const uint32_t* b) {
    asm("mma.sync.aligned.m16n8k8.row.col.f32.tf32.tf32.f32 "
        "{%0,%1,%2,%3}, {%4,%5,%6,%7}, {%8,%9}, {%0,%1,%2,%3};"
        : "+f"(d[0]), "+f"(d[1]), "+f"(d[2]), "+f"(d[3])
        : "r"(a[0]), "r"(a[1]), "r"(a[2]), "r"(a[3]), "r"(b[0]), "r"(b[1]));
}
__device__ __forceinline__ void mma3(float* d, const uint32_t* ah, const uint32_t* al,
                                     const uint32_t* bh, const uint32_t* bl) {
    mma8(d, ah, bh);
    mma8(d, ah, bl);
    mma8(d, al, bh);
}

// ================= K1: S GEMM (3xTF32) + dots + stats =================
// grid = BB*16, block 256 (8 warps = 4m x 2n). Tile: 64 i x 128 j.
__global__ __launch_bounds__(256, 2) void s_kernel(
    const float* __restrict__ Cg, const float* __restrict__ Qg,
    const float* __restrict__ w_mul, const float* __restrict__ w_c,
    const float* __restrict__ w_q, const float* __restrict__ bias,
    const int* __restrict__ Qmask, const int* __restrict__ Cmask) {
    __shared__ float buf[64 * 132];          // union: {As[64][36], Qs[128][36]} / Ss[64][132]
    __shared__ float s_cd[64], s_qd[128];
    __shared__ float s_m2[128], s_s2[128];
    __shared__ int s_qm[128], s_cm[64];
    float* As = buf;                 // [64][36] m-major (i, k)
    float* Qs = buf + 64 * 36;       // [128][36] n-major (j, k)

    int bx = blockIdx.x;
    int b = bx >> 4, tile = bx & 15, i0 = tile << 6;
    int t = threadIdx.x, wid = t >> 5, lane = t & 31;
    int g = lane >> 2, tg = lane & 3;
    int wm = wid & 3, wn = wid >> 2;
    int mb = wm << 4;          // 0..48
    int jb = wn << 6;          // 0 / 64

    if (t < 128) s_qm[t] = Qmask[b * LQ + t];
    if (t < 64)  s_cm[t] = Cmask[b * LC + i0 + t];

    float acc[8][4];
    #pragma unroll
    for (int nt = 0; nt < 8; nt++)
        #pragma unroll
        for (int e = 0; e < 4; e++) acc[nt][e] = 0.f;

    const float* Cb = Cg + ((size_t)b * LC + i0) * DD;
    const float* Qb = Qg + (size_t)b * LQ * DD;
    int li = t >> 2, lk = (t & 3) << 3;    // As loader
    int qj = t >> 1, qk = (t & 1) << 4;    // Qs loader
    float cdp = 0.f, qdp = 0.f;

    for (int kk = 0; kk < DD; kk += 32) {
        {   // As = C * w_mul ; accumulate cdot partial
            const float* src = Cb + (size_t)li * DD + kk + lk;
            float4 v0 = *(const float4*)src;
            float4 v1 = *(const float4*)(src + 4);
            float4 m0 = *(const float4*)(w_mul + kk + lk);
            float4 m1 = *(const float4*)(w_mul + kk + lk + 4);
            float4 c0 = *(const float4*)(w_c + kk + lk);
            float4 c1 = *(const float4*)(w_c + kk + lk + 4);
            cdp += v0.x * c0.x + v0.y * c0.y + v0.z * c0.z + v0.w * c0.w
                 + v1.x * c1.x + v1.y * c1.y + v1.z * c1.z + v1.w * c1.w;
            float* ar = As + li * 36 + lk;
            ar[0] = v0.x * m0.x; ar[1] = v0.y * m0.y; ar[2] = v0.z * m0.z; ar[3] = v0.w * m0.w;
            ar[4] = v1.x * m1.x; ar[5] = v1.y * m1.y; ar[6] = v1.z * m1.z; ar[7] = v1.w * m1.w;
        }
        {   // Qs ; accumulate qdot partial
            const float* src = Qb + (size_t)qj * DD + kk + qk;
            float* qr = Qs + qj * 36 + qk;
            #pragma unroll
            for (int u = 0; u < 16; u += 4) {
                float4 v = *(const float4*)(src + u);
                float4 w = *(const float4*)(w_q + kk + qk + u);
                qdp += v.x * w.x + v.y * w.y + v.z * w.z + v.w * w.w;
                qr[u] = v.x; qr[u + 1] = v.y; qr[u + 2] = v.z; qr[u + 3] = v.w;
            }
        }
        __syncthreads();
        #pragma unroll
        for (int k8 = 0; k8 < 4; k8++) {
            int kb = k8 << 3;
            uint32_t ah[4], al[4];
            split_tf32(As[(mb + g) * 36 + kb + tg],         ah[0], al[0]);
            split_tf32(As[(mb + g + 8) * 36 + kb + tg],     ah[1], al[1]);
            split_tf32(As[(mb + g) * 36 + kb + tg + 4],     ah[2], al[2]);
            split_tf32(As[(mb + g + 8) * 36 + kb + tg + 4], ah[3], al[3]);
            #pragma unroll
            for (int nt = 0; nt < 8; nt++) {
                uint32_t bh[2], bl[2];
                split_tf32(Qs[(jb + nt * 8 + g) * 36 + kb + tg],     bh[0], bl[0]);
                split_tf32(Qs[(jb + nt * 8 + g) * 36 + kb + tg + 4], bh[1], bl[1]);
                mma3(acc[nt], ah, al, bh, bl);
            }
        }
        __syncthreads();
    }

    // reduce dots
    cdp += __shfl_xor_sync(0xffffffffu, cdp, 1);
    cdp += __shfl_xor_sync(0xffffffffu, cdp, 2);
    if ((t & 3) == 0) s_cd[li] = cdp;
    qdp += __shfl_xor_sync(0xffffffffu, qdp, 1);
    if ((t & 1) == 0) s_qd[qj] = qdp;
    __syncthreads();

    // finalize into Ss
    float* Ss = buf;   // [64][132]
    {
        float bi = bias[0];
        float cd0 = s_cd[mb + g] + bi, cd1 = s_cd[mb + g + 8] + bi;
        #pragma unroll
        for (int nt = 0; nt < 8; nt++) {
            int c0 = jb + nt * 8 + 2 * tg;
            float q0 = s_qd[c0], q1 = s_qd[c0 + 1];
            Ss[(mb + g) * 132 + c0]     = acc[nt][0] + cd0 + q0;
            Ss[(mb + g) * 132 + c0 + 1] = acc[nt][1] + cd0 + q1;
            Ss[(mb + g + 8) * 132 + c0]     = acc[nt][2] + cd1 + q0;
            Ss[(mb + g + 8) * 132 + c0 + 1] = acc[nt][3] + cd1 + q1;
        }
    }
    __syncthreads();

    // phase A: row stats (qmask) + store g_S
    {
        int i = t >> 2, j0 = (t & 3) << 5;
        float mx = NEG;
        float* dst = g_S + ((size_t)(b * LC + i0 + i)) * LQ + j0;
        #pragma unroll
        for (int u = 0; u < 32; u += 4) {
            float4 v = *(const float4*)&Ss[i * 132 + j0 + u];
            int4 m = *(const int4*)&s_qm[j0 + u];
            *(float4*)(dst + u) = v;
            mx = fmaxf(mx, fmaxf(fmaxf(m.x ? v.x : NEG, m.y ? v.y : NEG),
                                 fmaxf(m.z ? v.z : NEG, m.w ? v.w : NEG)));
        }
        mx = fmaxf(mx, __shfl_xor_sync(0xffffffffu, mx, 1));
        mx = fmaxf(mx, __shfl_xor_sync(0xffffffffu, mx, 2));
        float sm = 0.f;
        #pragma unroll
        for (int u = 0; u < 32; u += 4) {
            float4 v = *(const float4*)&Ss[i * 132 + j0 + u];
            int4 m = *(const int4*)&s_qm[j0 + u];
            sm += __expf((m.x ? v.x : NEG) - mx) + __expf((m.y ? v.y : NEG) - mx)
                + __expf((m.z ? v.z : NEG) - mx) + __expf((m.w ? v.w : NEG) - mx);
        }
        sm += __shfl_xor_sync(0xffffffffu, sm, 1);
        sm += __shfl_xor_sync(0xffffffffu, sm, 2);
        if ((t & 3) == 0) {
            g_rmax[b * LC + i0 + i] = mx;
            g_rinv[b * LC + i0 + i] = 1.f / sm;
        }
    }

    // phase B: column partials (cmask) over this tile's 64 rows
    {
        int j = t & 127, ih = t >> 7;
        float m = NEG, s = 0.f;
        #pragma unroll 4
        for (int r = 0; r < 32; r++) {
            int i = ih * 32 + r;
            float v = s_cm[i] ? Ss[i * 132 + j] : NEG;
            float mn = fmaxf(m, v);
            s = s * __expf(m - mn) + __expf(v - mn);
            m = mn;
        }
        if (ih == 1) { s_m2[j] = m; s_s2[j] = s; }
        __syncthreads();
        if (ih == 0) {
            float m2 = s_m2[j], s2 = s_s2[j];
            float M = fmaxf(m, m2);
            float S = s * __expf(m - M) + s2 * __expf(m2 - M);
            g_cpm[(b * 16 + tile) * LQ + j] = M;
            g_cps[(b * 16 + tile) * LQ + j] = S;
        }
    }
}

// ================= K2: merge column partials =================
__global__ __launch_bounds__(256) void colmerge_kernel() {
    int idx = blockIdx.x * blockDim.x + threadIdx.x;
    if (idx >= BB * LQ) return;
    int b = idx >> 7, j = idx & 127;
    float M = NEG;
    #pragma unroll
    for (int g = 0; g < 16; g++) M = fmaxf(M, g_cpm[(b * 16 + g) * LQ + j]);
    float S = 0.f;
    #pragma unroll
    for (int g = 0; g < 16; g++) S += g_cps[(b * 16 + g) * LQ + j] * __expf(g_cpm[(b * 16 + g) * LQ + j] - M);
    g_cmax[idx] = M;
    g_cinv[idx] = 1.f / S;
}

// ================= K3: V2 partial = P2^T(chunk) @ C(chunk), 3xTF32 =====
// grid = BB*8, block 256 (8 warps = 4m x 2n). M=128 j, N=128 d, K=128 i.
__global__ __launch_bounds__(256, 2) void v2_kernel(
    const float* __restrict__ Cg, const int* __restrict__ Cmask) {
    __shared__ float Ps[32 * 136];   // k-major: [i'][j]
    __shared__ float Cs[32 * 136];   // k-major: [i'][d]
    __shared__ float s_cx[128], s_ci[128];
    __shared__ int s_cm[128];
    int b = blockIdx.x >> 3, gc = blockIdx.x & 7;
    int t = threadIdx.x, wid = t >> 5, lane = t & 31;
    int g = lane >> 2, tg = lane & 3;
    int wm = wid >> 1, wn = wid & 1;
    int mb0 = wm << 5;   // j base (m32 per warp)
    int nb = wn << 6;    // d base (n64)
    if (t < 128) {
        s_cx[t] = g_cmax[b * LQ + t];
        s_ci[t] = g_cinv[b * LQ + t];
        s_cm[t] = Cmask[b * LC + gc * 128 + t];
    }
    __syncthreads();

    float acc[2][8][4];
    #pragma unroll
    for (int mt = 0; mt < 2; mt++)
        #pragma unroll
        for (int nt = 0; nt < 8; nt++)
            #pragma unroll
            for (int e = 0; e < 4; e++) acc[mt][nt][e] = 0.f;

    int li = t >> 3, lj = (t & 7) << 4;
    for (int ik = 0; ik < 128; ik += 32) {
        {
            const float* srow = g_S + ((size_t)(b * LC + gc * 128 + ik + li)) * LQ + lj;
            int msk = s_cm[ik + li];
            float* pr = Ps + li * 136 + lj;
            #pragma unroll
            for (int u = 0; u < 16; u += 4) {
                float4 v = *(const float4*)(srow + u);
                pr[u]     = __expf((msk ? v.x : NEG) - s_cx[lj + u])     * s_ci[lj + u];
                pr[u + 1] = __expf((msk ? v.y : NEG) - s_cx[lj + u + 1]) * s_ci[lj + u + 1];
                pr[u + 2] = __expf((msk ? v.z : NEG) - s_cx[lj + u + 2]) * s_ci[lj + u + 2];
                pr[u + 3] = __expf((msk ? v.w : NEG) - s_cx[lj + u + 3]) * s_ci[lj + u + 3];
            }
            const float* crow = Cg + ((size_t)(b * LC + gc * 128 + ik + li)) * DD + lj;
            float* cr = Cs + li * 136 + lj;
            #pragma unroll
            for (int u = 0; u < 16; u += 4) {
                float4 v = *(const float4*)(crow + u);
                cr[u] = v.x; cr[u + 1] = v.y; cr[u + 2] = v.z; cr[u + 3] = v.w;
            }
        }
        __syncthreads();
        #pragma unroll
        for (int k8 = 0; k8 < 4; k8++) {
            int kb = k8 << 3;
            uint32_t ah[2][4], al[2][4];
            #pragma unroll
            for (int mt = 0; mt < 2; mt++) {
                int m0 = mb0 + mt * 16;
                split_tf32(Ps[(kb + tg) * 136 + m0 + g],         ah[mt][0], al[mt][0]);
                split_tf32(Ps[(kb + tg) * 136 + m0 + g + 8],     ah[mt][1], al[mt][1]);
                split_tf32(Ps[(kb + tg + 4) * 136 + m0 + g],     ah[mt][2], al[mt][2]);
                split_tf32(Ps[(kb + tg + 4) * 136 + m0 + g + 8], ah[mt][3], al[mt][3]);
            }
            #pragma unroll
            for (int nt = 0; nt < 8; nt++) {
                uint32_t bh[2], bl[2];
                split_tf32(Cs[(kb + tg) * 136 + nb + nt * 8 + g],     bh[0], bl[0]);
                split_tf32(Cs[(kb + tg + 4) * 136 + nb + nt * 8 + g], bh[1], bl[1]);
                mma3(acc[0][nt], ah[0], al[0], bh, bl);
                mma3(acc[1][nt], ah[1], al[1], bh, bl);
            }
        }
        __syncthreads();
    }

    float* Vp = g_V2p + (size_t)(b * 8 + gc) * LQ * DD;
    #pragma unroll
    for (int mt = 0; mt < 2; mt++) {
        int r0 = mb0 + mt * 16 + g;
        #pragma unroll
        for (int nt = 0; nt < 8; nt++) {
            int d = nb + nt * 8 + 2 * tg;
            *(float2*)(Vp + (size_t)r0 * DD + d)       = make_float2(acc[mt][nt][0], acc[mt][nt][1]);
            *(float2*)(Vp + (size_t)(r0 + 8) * DD + d) = make_float2(acc[mt][nt][2], acc[mt][nt][3]);
        }
    }
}

__global__ __launch_bounds__(256) void v2reduce_kernel() {
    int vec = blockIdx.x * blockDim.x + threadIdx.x;
    const int per_b = LQ * DD / 4;
    if (vec >= BB * per_b) return;
    int b = vec / per_b;
    int off = vec % per_b;
    float4 s = make_float4(0.f, 0.f, 0.f, 0.f);
    #pragma unroll
    for (int g = 0; g < 8; g++) {
        float4 v = ((const float4*)(g_V2p + (size_t)(b * 8 + g) * LQ * DD))[off];
        s.x += v.x; s.y += v.y; s.z += v.z; s.w += v.w;
    }
    ((float4*)g_V2)[vec] = s;
}

// ================= K4: A = P1@Q, Bm = P1@V2 (3xTF32), epilogue =========
// grid = BB*16, block 256 (8 warps = 4m x 2n per pass). Tile 64 i x 128 n.
__global__ __launch_bounds__(256, 2) void final_kernel(
    const float* __restrict__ Cg, const float* __restrict__ Qg,
    const int* __restrict__ Qmask, float* __restrict__ out) {
    __shared__ float Ps[64 * 132];   // m-major: [i][j], full K
    __shared__ float Bs[16 * 136];   // k-major chunk: [j'][d]
    int bx = blockIdx.x;
    int b = bx >> 4, i0 = (bx & 15) << 6;
    int t = threadIdx.x, wid = t >> 5, lane = t & 31;
    int g = lane >> 2, tg = lane & 3;
    int wm = wid & 3, wn = wid >> 2;
    int mb = wm << 4, nb = wn << 6;

    {   // build P1 tile
        int i = t >> 2, j0 = (t & 3) << 5;
        int gi = b * LC + i0 + i;
        float rm = __ldg(&g_rmax[gi]), ri = __ldg(&g_rinv[gi]);
        const float* srow = g_S + (size_t)gi * LQ + j0;
        const int* qm = Qmask + b * LQ + j0;
        float* pr = Ps + i * 132 + j0;
        #pragma unroll
        for (int u = 0; u < 32; u += 4) {
            float4 v = *(const float4*)(srow + u);
            int4 m = *(const int4*)(qm + u);
            pr[u]     = __expf((m.x ? v.x : NEG) - rm) * ri;
            pr[u + 1] = __expf((m.y ? v.y : NEG) - rm) * ri;
            pr[u + 2] = __expf((m.z ? v.z : NEG) - rm) * ri;
            pr[u + 3] = __expf((m.w ? v.w : NEG) - rm) * ri;
        }
    }
    __syncthreads();

    int lk = t >> 4, ld0 = (t & 15) << 3;
    #pragma unroll
    for (int pass = 0; pass < 2; pass++) {
        const float* Bsrc = pass ? (g_V2 + (size_t)b * LQ * DD) : (Qg + (size_t)b * LQ * DD);
        float acc[8][4];
        #pragma unroll
        for (int nt = 0; nt < 8; nt++)
            #pragma unroll
            for (int e = 0; e < 4; e++) acc[nt][e] = 0.f;

        for (int kk = 0; kk < LQ; kk += 16) {
            {
                const float* br = Bsrc + (size_t)(kk + lk) * DD + ld0;
                float4 v0 = *(const float4*)br;
                float4 v1 = *(const float4*)(br + 4);
                float* bd = Bs + lk * 136 + ld0;
                bd[0] = v0.x; bd[1] = v0.y; bd[2] = v0.z; bd[3] = v0.w;
                bd[4] = v1.x; bd[5] = v1.y; bd[6] = v1.z; bd[7] = v1.w;
            }
            __syncthreads();
            #pragma unroll
            for (int k8 = 0; k8 < 2; k8++) {
                int kb = k8 << 3;
                uint32_t ah[4], al[4];
                split_tf32(Ps[(mb + g) * 132 + kk + kb + tg],         ah[0], al[0]);
                split_tf32(Ps[(mb + g + 8) * 132 + kk + kb + tg],     ah[1], al[1]);
                split_tf32(Ps[(mb + g) * 132 + kk + kb + tg + 4],     ah[2], al[2]);
                split_tf32(Ps[(mb + g + 8) * 132 + kk + kb + tg + 4], ah[3], al[3]);
                #pragma unroll
                for (int nt = 0; nt < 8; nt++) {
                    uint32_t bh[2], bl[2];
                    split_tf32(Bs[(kb + tg) * 136 + nb + nt * 8 + g],     bh[0], bl[0]);
                    split_tf32(Bs[(kb + tg + 4) * 136 + nb + nt * 8 + g], bh[1], bl[1]);
                    mma3(acc[nt], ah, al, bh, bl);
                }
            }
            __syncthreads();
        }

        // epilogue
        int r0 = i0 + mb + g, r1 = r0 + 8;
        const float* c0p = Cg + ((size_t)(b * LC + r0)) * DD;
        const float* c1p = Cg + ((size_t)(b * LC + r1)) * DD;
        float* o0 = out + ((size_t)(b * LC + r0)) * (4 * DD);
        float* o1 = out + ((size_t)(b * LC + r1)) * (4 * DD);
        #pragma unroll
        for (int nt = 0; nt < 8; nt++) {
            int d = nb + nt * 8 + 2 * tg;
            float2 c0 = *(const float2*)(c0p + d);
            float2 c1 = *(const float2*)(c1p + d);
            if (pass == 0) {
                *(float2*)(o0 + d) = c0;
                *(float2*)(o1 + d) = c1;
                *(float2*)(o0 + DD + d) = make_float2(acc[nt][0], acc[nt][1]);
                *(float2*)(o1 + DD + d) = make_float2(acc[nt][2], acc[nt][3]);
                *(float2*)(o0 + 2 * DD + d) = make_float2(c0.x * acc[nt][0], c0.y * acc[nt][1]);
                *(float2*)(o1 + 2 * DD + d) = make_float2(c1.x * acc[nt][2], c1.y * acc[nt][3]);
            } else {
                *(float2*)(o0 + 3 * DD + d) = make_float2(c0.x * acc[nt][0], c0.y * acc[nt][1]);
                *(float2*)(o1 + 3 * DD + d) = make_float2(c1.x * acc[nt][2], c1.y * acc[nt][3]);
            }
        }
    }
}

// ---------------- launch ----------------
extern "C" void kernel_launch(void* const* d_in, const int* in_sizes, int n_in,
                              void* d_out, int out_size) {
    const float* C     = (const float*)d_in[0];
    const float* Q     = (const float*)d_in[1];
    const int*   Cmask = (const int*)d_in[2];
    const int*   Qmask = (const int*)d_in[3];
    const float* w_c   = (const float*)d_in[4];
    const float* w_q   = (const float*)d_in[5];
    const float* w_mul = (const float*)d_in[6];
    const float* bias  = (const float*)d_in[7];
    float* out = (float*)d_out;

    s_kernel<<<BB * 16, 256>>>(C, Q, w_mul, w_c, w_q, bias, Qmask, Cmask);
    colmerge_kernel<<<(BB * LQ + 255) / 256, 256>>>();
    v2_kernel<<<BB * 8, 256>>>(C, Cmask);
    v2reduce_kernel<<<(BB * LQ * DD / 4 + 255) / 256, 256>>>();
    final_kernel<<<BB * 16, 256>>>(C, Q, Qmask, out);
}